// round 11
// baseline (speedup 1.0000x reference)
#include <cuda_runtime.h>

#define PP    30
#define SS    224
#define CROPN 164
#define BB    16
#define TT    16
#define BATCH 16
#define PLANE  (SS * SS)        // 50176
#define PLANE4 (PLANE / 4)      // 12544

// PyTorch bilinear (align_corners=False) 1D index/weight, mirroring the
// reference float32 op order exactly.
__device__ __forceinline__ void interp1d(float pos, float in_size, float out_size,
                                         int in_max, int& i0, int& i1, float& w) {
    float scale = in_size / out_size;
    float f = fmaxf((pos + 0.5f) * scale - 0.5f, 0.0f);
    float fi = floorf(f);
    i0 = (int)fi;
    w  = f - fi;
    i1 = min(i0 + 1, in_max);
}

__global__ void __launch_bounds__(64)
prompt_add_kernel(const float* __restrict__ x,
                  const float* __restrict__ pad_up,     // [3,3,60,224]
                  const float* __restrict__ pad_down,   // [3,3,30,224]
                  const float* __restrict__ pad_left,   // [3,3,164,60]
                  const float* __restrict__ pad_right,  // [3,3,164,30]
                  const int*   __restrict__ cam_views,
                  const int*   __restrict__ offsets_right,
                  const int*   __restrict__ offsets_down,
                  float* __restrict__ out)
{
    int g = blockIdx.x * blockDim.x + threadIdx.x;   // [0, B*3*PLANE4)
    int bc     = g / PLANE4;
    int within = g - bc * PLANE4;
    int b = bc / 3;
    int c = bc - b * 3;
    int pix = within * 4;
    int i  = pix / SS;
    int j0 = pix - i * SS;

    int cam = cam_views[b];
    int orr = offsets_right[b];
    int od  = offsets_down[b];
    int off_l = 2 * PP - orr;
    int off_u = 2 * PP - od;

    float p0, p1, p2, p3;

    if (i < off_u) {
        // rows interpolated from pad_up (in=60, out=off_u)
        int r0, r1; float wv;
        interp1d((float)i, 2.0f * PP, (float)off_u, 2 * PP - 1, r0, r1, wv);
        const float* base = pad_up + ((cam * 3 + c) * (2 * PP)) * SS;
        float4 a  = *(const float4*)(base + r0 * SS + j0);
        float4 bt = *(const float4*)(base + r1 * SS + j0);
        float om = 1.0f - wv;
        p0 = a.x * om + bt.x * wv;
        p1 = a.y * om + bt.y * wv;
        p2 = a.z * om + bt.z * wv;
        p3 = a.w * om + bt.w * wv;
    } else if (i >= SS - od) {
        // rows interpolated from pad_down (in=30, out=od)
        int r0, r1; float wv;
        interp1d((float)(i - (SS - od)), (float)PP, (float)od, PP - 1, r0, r1, wv);
        const float* base = pad_down + ((cam * 3 + c) * PP) * SS;
        float4 a  = *(const float4*)(base + r0 * SS + j0);
        float4 bt = *(const float4*)(base + r1 * SS + j0);
        float om = 1.0f - wv;
        p0 = a.x * om + bt.x * wv;
        p1 = a.y * om + bt.y * wv;
        p2 = a.z * om + bt.z * wv;
        p3 = a.w * om + bt.w * wv;
    } else {
        // middle band: horizontal interpolation from pad_left / pad_right, or 0
        int rr = i - off_u;                       // [0, CROP)
        const float* plrow = pad_left  + ((cam * 3 + c) * CROPN + rr) * (2 * PP);
        const float* prrow = pad_right + ((cam * 3 + c) * CROPN + rr) * PP;
        float pv[4];
        #pragma unroll
        for (int k = 0; k < 4; k++) {
            int j = j0 + k;
            float v = 0.0f;
            if (j < off_l) {
                int i0h, i1h; float w;
                interp1d((float)j, 2.0f * PP, (float)off_l, 2 * PP - 1, i0h, i1h, w);
                v = plrow[i0h] * (1.0f - w) + plrow[i1h] * w;
            } else if (j >= SS - orr) {
                int i0h, i1h; float w;
                interp1d((float)(j - (SS - orr)), (float)PP, (float)orr, PP - 1, i0h, i1h, w);
                v = prrow[i0h] * (1.0f - w) + prrow[i1h] * w;
            }
            pv[k] = v;
        }
        p0 = pv[0]; p1 = pv[1]; p2 = pv[2]; p3 = pv[3];
    }

    // stream all T frames: 16 independent front-batched LDG.128 (8 KB in
    // flight per thread), then 16 add+stores. Streaming hints: touched once.
    size_t base4 = (size_t)bc * TT * PLANE4 + within;
    const float4* xp = (const float4*)x + base4;
    float4*       op = (float4*)out + base4;
    float4 v[BATCH];
    #pragma unroll
    for (int u = 0; u < BATCH; u++)
        v[u] = __ldcs(xp + (size_t)u * PLANE4);
    #pragma unroll
    for (int u = 0; u < BATCH; u++) {
        v[u].x += p0; v[u].y += p1; v[u].z += p2; v[u].w += p3;
        __stcs(op + (size_t)u * PLANE4, v[u]);
    }
}

extern "C" void kernel_launch(void* const* d_in, const int* in_sizes, int n_in,
                              void* d_out, int out_size) {
    const float* x         = (const float*)d_in[0];
    const float* pad_up    = (const float*)d_in[1];
    const float* pad_down  = (const float*)d_in[2];
    const float* pad_left  = (const float*)d_in[3];
    const float* pad_right = (const float*)d_in[4];
    const int*   cam_views = (const int*)d_in[5];
    const int*   off_r     = (const int*)d_in[6];
    const int*   off_d     = (const int*)d_in[7];
    float* out = (float*)d_out;

    const int total = BB * 3 * PLANE4;   // 602112
    const int block = 64;
    const int grid  = total / block;     // 9408, exact
    prompt_add_kernel<<<grid, block>>>(x, pad_up, pad_down, pad_left, pad_right,
                                       cam_views, off_r, off_d, out);
}

// round 14
// speedup vs baseline: 1.0174x; 1.0174x over previous
#include <cuda_runtime.h>

#define PP    30
#define SS    224
#define CROPN 164
#define BB    16
#define TT    16
#define BATCH 16
#define PLANE  (SS * SS)        // 50176
#define PLANE4 (PLANE / 4)      // 12544

// PyTorch bilinear (align_corners=False) 1D index/weight, mirroring the
// reference float32 op order exactly.
__device__ __forceinline__ void interp1d(float pos, float in_size, float out_size,
                                         int in_max, int& i0, int& i1, float& w) {
    float scale = in_size / out_size;
    float f = fmaxf((pos + 0.5f) * scale - 0.5f, 0.0f);
    float fi = floorf(f);
    i0 = (int)fi;
    w  = f - fi;
    i1 = min(i0 + 1, in_max);
}

__global__ void __launch_bounds__(128)
prompt_add_kernel(const float* __restrict__ x,
                  const float* __restrict__ pad_up,     // [3,3,60,224]
                  const float* __restrict__ pad_down,   // [3,3,30,224]
                  const float* __restrict__ pad_left,   // [3,3,164,60]
                  const float* __restrict__ pad_right,  // [3,3,164,30]
                  const int*   __restrict__ cam_views,
                  const int*   __restrict__ offsets_right,
                  const int*   __restrict__ offsets_down,
                  float* __restrict__ out)
{
    int g = blockIdx.x * blockDim.x + threadIdx.x;   // [0, B*3*PLANE4)
    int bc     = g / PLANE4;
    int within = g - bc * PLANE4;
    int b = bc / 3;
    int c = bc - b * 3;
    int pix = within * 4;
    int i  = pix / SS;
    int j0 = pix - i * SS;

    int cam = cam_views[b];
    int orr = offsets_right[b];
    int od  = offsets_down[b];
    int off_l = 2 * PP - orr;
    int off_u = 2 * PP - od;

    float p0, p1, p2, p3;

    if (i < off_u) {
        // rows interpolated from pad_up (in=60, out=off_u)
        int r0, r1; float wv;
        interp1d((float)i, 2.0f * PP, (float)off_u, 2 * PP - 1, r0, r1, wv);
        const float* base = pad_up + ((cam * 3 + c) * (2 * PP)) * SS;
        float4 a  = *(const float4*)(base + r0 * SS + j0);
        float4 bt = *(const float4*)(base + r1 * SS + j0);
        float om = 1.0f - wv;
        p0 = a.x * om + bt.x * wv;
        p1 = a.y * om + bt.y * wv;
        p2 = a.z * om + bt.z * wv;
        p3 = a.w * om + bt.w * wv;
    } else if (i >= SS - od) {
        // rows interpolated from pad_down (in=30, out=od)
        int r0, r1; float wv;
        interp1d((float)(i - (SS - od)), (float)PP, (float)od, PP - 1, r0, r1, wv);
        const float* base = pad_down + ((cam * 3 + c) * PP) * SS;
        float4 a  = *(const float4*)(base + r0 * SS + j0);
        float4 bt = *(const float4*)(base + r1 * SS + j0);
        float om = 1.0f - wv;
        p0 = a.x * om + bt.x * wv;
        p1 = a.y * om + bt.y * wv;
        p2 = a.z * om + bt.z * wv;
        p3 = a.w * om + bt.w * wv;
    } else {
        // middle band: horizontal interpolation from pad_left / pad_right, or 0
        int rr = i - off_u;                       // [0, CROP)
        const float* plrow = pad_left  + ((cam * 3 + c) * CROPN + rr) * (2 * PP);
        const float* prrow = pad_right + ((cam * 3 + c) * CROPN + rr) * PP;
        float pv[4];
        #pragma unroll
        for (int k = 0; k < 4; k++) {
            int j = j0 + k;
            float v = 0.0f;
            if (j < off_l) {
                int i0h, i1h; float w;
                interp1d((float)j, 2.0f * PP, (float)off_l, 2 * PP - 1, i0h, i1h, w);
                v = plrow[i0h] * (1.0f - w) + plrow[i1h] * w;
            } else if (j >= SS - orr) {
                int i0h, i1h; float w;
                interp1d((float)(j - (SS - orr)), (float)PP, (float)orr, PP - 1, i0h, i1h, w);
                v = prrow[i0h] * (1.0f - w) + prrow[i1h] * w;
            }
            pv[k] = v;
        }
        p0 = pv[0]; p1 = pv[1]; p2 = pv[2]; p3 = pv[3];
    }

    // stream all T frames: 16 independent front-batched LDG.128 (8 KB in
    // flight per thread), then 16 add+stores. Streaming hints: touched once.
    size_t base4 = (size_t)bc * TT * PLANE4 + within;
    const float4* xp = (const float4*)x + base4;
    float4*       op = (float4*)out + base4;
    float4 v[BATCH];
    #pragma unroll
    for (int u = 0; u < BATCH; u++)
        v[u] = __ldcs(xp + (size_t)u * PLANE4);
    #pragma unroll
    for (int u = 0; u < BATCH; u++) {
        v[u].x += p0; v[u].y += p1; v[u].z += p2; v[u].w += p3;
        __stcs(op + (size_t)u * PLANE4, v[u]);
    }
}

extern "C" void kernel_launch(void* const* d_in, const int* in_sizes, int n_in,
                              void* d_out, int out_size) {
    const float* x         = (const float*)d_in[0];
    const float* pad_up    = (const float*)d_in[1];
    const float* pad_down  = (const float*)d_in[2];
    const float* pad_left  = (const float*)d_in[3];
    const float* pad_right = (const float*)d_in[4];
    const int*   cam_views = (const int*)d_in[5];
    const int*   off_r     = (const int*)d_in[6];
    const int*   off_d     = (const int*)d_in[7];
    float* out = (float*)d_out;

    const int total = BB * 3 * PLANE4;   // 602112
    const int block = 128;
    const int grid  = total / block;     // 4704, exact
    prompt_add_kernel<<<grid, block>>>(x, pad_up, pad_down, pad_left, pad_right,
                                       cam_views, off_r, off_d, out);
}